// round 16
// baseline (speedup 1.0000x reference)
#include <cuda_runtime.h>
#include <cuda_fp16.h>

typedef unsigned int u32;

#define BATCH 2
#define SEQ   2048
#define DM    1024
#define NH    16
#define HD    64
#define MROWS 4096
#define BH    32

// Q pre-scale: (1/sqrt(64)) * log2(e) so softmax can use exp2
#define QSCALE 0.18033688011112042f

// ---------------------------------------------------------------------------
__device__ __align__(128) __half g_x  [(size_t)MROWS * DM];
__device__ __align__(128) __half g_Wh [(size_t)48 * HD * DM];  // [(proj*16+h)*64+e][d]
__device__ __align__(128) __half g_Wp [(size_t)DM * DM];       // [n][k]
__device__ __align__(128) __half g_Q  [(size_t)BH * SEQ * HD]; // pre-scaled QSCALE
__device__ __align__(128) __half g_K  [(size_t)BH * SEQ * HD];
__device__ __align__(128) __half g_Vt [(size_t)BH * HD * SEQ]; // [bh][e][s]
__device__ __align__(128) __half g_C  [(size_t)MROWS * DM];

// ---------------------------------------------------------------------------
__device__ __forceinline__ u32 smem_u32(const void* p) {
    u32 a;
    asm("{ .reg .u64 t; cvta.to.shared.u64 t, %1; cvt.u32.u64 %0, t; }" : "=r"(a) : "l"(p));
    return a;
}
__device__ __forceinline__ void mma16816(float c[4], u32 a0, u32 a1, u32 a2, u32 a3,
                                         u32 b0, u32 b1) {
    asm volatile("mma.sync.aligned.m16n8k16.row.col.f32.f16.f16.f32 "
                 "{%0,%1,%2,%3},{%4,%5,%6,%7},{%8,%9},{%0,%1,%2,%3};"
                 : "+f"(c[0]), "+f"(c[1]), "+f"(c[2]), "+f"(c[3])
                 : "r"(a0), "r"(a1), "r"(a2), "r"(a3), "r"(b0), "r"(b1));
}
__device__ __forceinline__ void ldsm4(u32& r0, u32& r1, u32& r2, u32& r3, u32 addr) {
    asm volatile("ldmatrix.sync.aligned.m8n8.x4.shared.b16 {%0,%1,%2,%3},[%4];"
                 : "=r"(r0), "=r"(r1), "=r"(r2), "=r"(r3) : "r"(addr));
}
__device__ __forceinline__ void cpa16(u32 dst, const void* src) {
    asm volatile("cp.async.ca.shared.global [%0],[%1],16;" :: "r"(dst), "l"(src));
}
#define CP_COMMIT() asm volatile("cp.async.commit_group;" ::: "memory")
#define CP_WAIT0()  asm volatile("cp.async.wait_group 0;" ::: "memory")
#define CP_WAIT1()  asm volatile("cp.async.wait_group 1;" ::: "memory")

__device__ __forceinline__ u32 pack2(float a, float b) {
    __half2 h = __floats2half2_rn(a, b);
    return *reinterpret_cast<u32*>(&h);
}
__device__ __forceinline__ u32 exp2x2(float d0, float d1) {
    u32 h = pack2(d0, d1), r;
    asm("ex2.approx.f16x2 %0, %1;" : "=r"(r) : "r"(h));
    return r;
}

// ---------------------------------------------------------------------------
// Prep
// ---------------------------------------------------------------------------
__global__ void k_prep(const float* __restrict__ x, const float* __restrict__ Wp) {
    int i = blockIdx.x * 256 + threadIdx.x;
    if (i < MROWS * DM) g_x[i] = __float2half_rn(x[i]);
    int j = i - MROWS * DM;
    if (j >= 0 && j < DM * DM) g_Wp[j] = __float2half_rn(Wp[j]);
}
__global__ void k_split_w_t(const float* __restrict__ Wq, const float* __restrict__ Wk,
                            const float* __restrict__ Wv) {
    __shared__ float t[32][33];
    int d0 = blockIdx.x * 32, e0 = blockIdx.y * 32;
    int ph = blockIdx.z, proj = ph >> 4, h = ph & 15;
    const float* W = (proj == 0) ? Wq : (proj == 1) ? Wk : Wv;
    const float* src = W + ((size_t)h * DM + d0) * HD + e0;
    for (int j = threadIdx.y; j < 32; j += 8)
        t[j][threadIdx.x] = src[(size_t)j * HD + threadIdx.x];
    __syncthreads();
    size_t ob = ((size_t)ph * HD + e0) * DM + d0;
    for (int j = threadIdx.y; j < 32; j += 8)
        g_Wh[ob + (size_t)j * DM + threadIdx.x] = __float2half_rn(t[threadIdx.x][j]);
}

// ---------------------------------------------------------------------------
// GEMM 256(M) x 128(N) x 1024, BK=32, 8 warps (4M x 2N), warp tile 64x64.
// 3-stage cp.async ring, one __syncthreads per chunk. 1 CTA/SM.
// smem halves per stage: A 256x40 (10240), B 128x40 (5120); stride 15360.
// ---------------------------------------------------------------------------
#define P_STAGE 15360
#define P_SMEM_BYTES (3 * P_STAGE * 2)

__device__ __forceinline__ void proj_issue(u32 smb, const __half* A, const __half* B,
                                           int k0, int stage, int tid)
{
    u32 a = smb + (stage * P_STAGE) * 2;
    u32 b = a + 10240 * 2;
    #pragma unroll
    for (int i = tid; i < 1536; i += 256) {
        if (i < 1024) {
            int r = i >> 2, c8 = (i & 3) * 8;
            cpa16(a + (r * 40 + c8) * 2, A + (size_t)r * DM + k0 + c8);
        } else {
            int j = i - 1024, r = j >> 2, c8 = (j & 3) * 8;
            cpa16(b + (r * 40 + c8) * 2, B + (size_t)r * DM + k0 + c8);
        }
    }
}

__device__ __forceinline__ void proj_compute(u32 smb, int stage, int lane, int wm, int wn,
                                             float acc[4][8][4])
{
    u32 aB = smb + (stage * P_STAGE) * 2;
    u32 bB = aB + 10240 * 2;
    #pragma unroll
    for (int kk = 0; kk < 32; kk += 16) {
        u32 a4[4][4];
        int arow_off = ((wm * 64 + (lane & 15)) * 40 + kk + ((lane >> 4) << 3)) * 2;
        #pragma unroll
        for (int mt = 0; mt < 4; mt++)
            ldsm4(a4[mt][0], a4[mt][1], a4[mt][2], a4[mt][3], aB + arow_off + mt * 16 * 40 * 2);
        int nbase = wn * 64 + ((lane >> 4) << 3) + (lane & 7);
        int koff = kk + (((lane >> 3) & 1) << 3);
        #pragma unroll
        for (int nt2 = 0; nt2 < 4; nt2++) {
            u32 b4[4];
            ldsm4(b4[0], b4[1], b4[2], b4[3], bB + ((nbase + nt2 * 16) * 40 + koff) * 2);
            #pragma unroll
            for (int hn = 0; hn < 2; hn++) {
                int nt = nt2 * 2 + hn;
                #pragma unroll
                for (int mt = 0; mt < 4; mt++)
                    mma16816(acc[mt][nt], a4[mt][0], a4[mt][1], a4[mt][2], a4[mt][3],
                             b4[hn * 2], b4[hn * 2 + 1]);
            }
        }
    }
}

__device__ __forceinline__ void proj_mainloop(u32 smb, const __half* A, const __half* B,
                                              float acc[4][8][4], int tid, int lane,
                                              int wm, int wn)
{
    proj_issue(smb, A, B, 0, 0, tid);
    CP_COMMIT();
    proj_issue(smb, A, B, 32, 1, tid);
    CP_COMMIT();
    for (int st = 0; st < 32; st++) {
        if (st < 31) CP_WAIT1(); else CP_WAIT0();
        __syncthreads();
        if (st + 2 < 32) {
            proj_issue(smb, A, B, (st + 2) * 32, (st + 2) % 3, tid);
            CP_COMMIT();
        }
        proj_compute(smb, st % 3, lane, wm, wn, acc);
    }
    __syncthreads();   // protect smem reuse by epilogue
}

// ---------------------------------------------------------------------------
// QKV GEMM: grid (16 m-tiles, 24). All 1-pass fp16.
// ---------------------------------------------------------------------------
__global__ __launch_bounds__(256, 1)
void k_gemm_qkv(const float* __restrict__ bq, const float* __restrict__ bk,
                const float* __restrict__ bv)
{
    extern __shared__ char smch[];
    u32 smb = smem_u32(smch);
    int tid = threadIdx.x, lane = tid & 31, wid = tid >> 5;
    int wm = wid >> 1, wn = wid & 1;

    int m0 = blockIdx.x * 256;
    int py = blockIdx.y, proj = py >> 3, n0 = (py & 7) * 128;

    const __half* B = g_Wh + ((size_t)proj * 16 * HD + n0) * DM;

    float acc[4][8][4] = {};
    proj_mainloop(smb, g_x + (size_t)m0 * DM, B, acc, tid, lane, wm, wn);

    const float* bias = ((proj == 0) ? bq : (proj == 1 ? bk : bv));

    if (proj < 2) {
        float scale = (proj == 0) ? QSCALE : 1.0f;
        __half* oq = (proj == 0 ? g_Q : g_K);
        #pragma unroll
        for (int mt = 0; mt < 4; mt++) {
            #pragma unroll
            for (int nt = 0; nt < 8; nt++) {
                int m = m0 + wm * 64 + mt * 16 + (lane >> 2);
                int eg = n0 + wn * 64 + nt * 8 + (lane & 3) * 2;
                int h = eg >> 6, e = eg & 63;
                float be0 = bias[eg], be1 = bias[eg + 1];
                float v0 = (acc[mt][nt][0] + be0) * scale;
                float v1 = (acc[mt][nt][1] + be1) * scale;
                float v2 = (acc[mt][nt][2] + be0) * scale;
                float v3 = (acc[mt][nt][3] + be1) * scale;
                int b0 = m >> 11, s0 = m & 2047;
                int m2 = m + 8, b2 = m2 >> 11, s2 = m2 & 2047;
                *(u32*)(oq + ((size_t)(b0 * NH + h) * SEQ + s0) * HD + e) = pack2(v0, v1);
                *(u32*)(oq + ((size_t)(b2 * NH + h) * SEQ + s2) * HD + e) = pack2(v2, v3);
            }
        }
    } else {
        // V: stage transposed [128 e][256 m] tile in smem, coalesced stores
        __half* sv = (__half*)smch;
        #pragma unroll
        for (int mt = 0; mt < 4; mt++) {
            #pragma unroll
            for (int nt = 0; nt < 8; nt++) {
                int ml = wm * 64 + mt * 16 + (lane >> 2);
                int el = wn * 64 + nt * 8 + (lane & 3) * 2;
                float be0 = bias[n0 + el], be1 = bias[n0 + el + 1];
                sv[el * 256 + ml]            = __float2half_rn(acc[mt][nt][0] + be0);
                sv[(el + 1) * 256 + ml]      = __float2half_rn(acc[mt][nt][1] + be1);
                sv[el * 256 + ml + 8]        = __float2half_rn(acc[mt][nt][2] + be0);
                sv[(el + 1) * 256 + ml + 8]  = __float2half_rn(acc[mt][nt][3] + be1);
            }
        }
        __syncthreads();
        int b = m0 >> 11, s0 = m0 & 2047;
        for (int i = tid; i < 128 * 128; i += 256) {
            int el = i >> 7, mp = i & 127;
            int eg = n0 + el, h = eg >> 6, e = eg & 63;
            ((u32*)(g_Vt + ((size_t)(b * NH + h) * HD + e) * SEQ + s0))[mp]
                = ((u32*)(sv + el * 256))[mp];
        }
    }
}

// ---------------------------------------------------------------------------
// Flash attention: unchanged from round 14 (96 us, tensor 62%).
// ---------------------------------------------------------------------------
#define A_STAGE 10368
#define A_SMEM_BYTES ((9216 + 3 * A_STAGE) * 2)

__device__ __forceinline__ void attn_issue(u32 smb,
    const __half* K, const __half* V, int c0, int stage, int tid)
{
    u32 kb = smb + (9216 + stage * A_STAGE) * 2;
    u32 vb = kb + 4608 * 2;
    #pragma unroll
    for (int i = tid; i < 512; i += 128) {
        int r = i >> 3, c8 = (i & 7) * 8;
        cpa16(kb + (r * 72 + c8) * 2, K + (size_t)(c0 + r) * HD + c8);
        cpa16(vb + (r * 72 + c8) * 2, V + (size_t)r * SEQ + c0 + c8);
    }
}

__global__ __launch_bounds__(128, 2)
void k_attn()
{
    extern __shared__ char smch[];
    u32 smb = smem_u32(smch);
    int tid = threadIdx.x, lane = tid & 31, wid = tid >> 5;

    int q0 = blockIdx.x * 128;
    int bh = blockIdx.y;
    const __half* Qp = g_Q + (size_t)bh * SEQ * HD;
    const __half* Kp = g_K + (size_t)bh * SEQ * HD;
    const __half* Vp = g_Vt + (size_t)bh * HD * SEQ;

    attn_issue(smb, Kp, Vp, 0, 0, tid);
    CP_COMMIT();
    attn_issue(smb, Kp, Vp, 64, 1, tid);
    CP_COMMIT();

    #pragma unroll
    for (int i = tid; i < 1024; i += 128) {
        int r = i >> 3, c8 = (i & 7) * 8;
        *(uint4*)(smch + (r * 72 + c8) * 2) = *(const uint4*)(Qp + (size_t)(q0 + r) * HD + c8);
    }
    for (int i = tid; i < 3 * 16 * 72; i += 128) {
        int stage = i / (16 * 72), rem = i % (16 * 72);
        int row = 64 + rem / 72, col = rem % 72;
        __half v = (row == 64) ? __float2half_rn(1.0f) : __float2half_rn(0.0f);
        *(__half*)(smch + (9216 + stage * A_STAGE + 4608 + row * 72 + col) * 2) = v;
    }
    __syncthreads();

    u32 qf[2][4][4];
    #pragma unroll
    for (int mf = 0; mf < 2; mf++)
        #pragma unroll
        for (int ks = 0; ks < 4; ks++) {
            u32 qoff = smb + ((wid * 32 + mf * 16 + (lane & 15)) * 72
                              + ks * 16 + ((lane >> 4) << 3)) * 2;
            ldsm4(qf[mf][ks][0], qf[mf][ks][1], qf[mf][ks][2], qf[mf][ks][3], qoff);
        }

    float o[2][9][4] = {};

    for (int it = 0; it < 32; it++) {
        int buf = it % 3;
        if (it < 31) CP_WAIT1(); else CP_WAIT0();
        __syncthreads();
        if (it + 2 < 32) {
            attn_issue(smb, Kp, Vp, (it + 2) * 64, (it + 2) % 3, tid);
            CP_COMMIT();
        }

        float s[2][8][4] = {};
        u32 kB = smb + (9216 + buf * A_STAGE) * 2;
        int nbase = ((lane >> 4) << 3) + (lane & 7);
        #pragma unroll
        for (int ks = 0; ks < 4; ks++) {
            int koff = ks * 16 + (((lane >> 3) & 1) << 3);
            #pragma unroll
            for (int nt2 = 0; nt2 < 4; nt2++) {
                u32 k4[4];
                ldsm4(k4[0], k4[1], k4[2], k4[3], kB + ((nbase + nt2 * 16) * 72 + koff) * 2);
                #pragma unroll
                for (int mf = 0; mf < 2; mf++) {
                    mma16816(s[mf][nt2 * 2],     qf[mf][ks][0], qf[mf][ks][1],
                             qf[mf][ks][2], qf[mf][ks][3], k4[0], k4[1]);
                    mma16816(s[mf][nt2 * 2 + 1], qf[mf][ks][0], qf[mf][ks][1],
                             qf[mf][ks][2], qf[mf][ks][3], k4[2], k4[3]);
                }
            }
        }

        u32 pf[2][4][4];
        #pragma unroll
        for (int mf = 0; mf < 2; mf++)
            #pragma unroll
            for (int ks = 0; ks < 4; ks++) {
                int t0 = 2 * ks, t1 = 2 * ks + 1;
                pf[mf][ks][0] = exp2x2(s[mf][t0][0], s[mf][t0][1]);
                pf[mf][ks][1] = exp2x2(s[mf][t0][2], s[mf][t0][3]);
                pf[mf][ks][2] = exp2x2(s[mf][t1][0], s[mf][t1][1]);
                pf[mf][ks][3] = exp2x2(s[mf][t1][2], s[mf][t1][3]);
            }

        u32 vB = kB + 4608 * 2;
        #pragma unroll
        for (int ks = 0; ks < 4; ks++) {
            int koff = ks * 16 + (((lane >> 3) & 1) << 3);
            #pragma unroll
            for (int nt2 = 0; nt2 < 4; nt2++) {
                u32 v4[4];
                ldsm4(v4[0], v4[1], v4[2], v4[3], vB + ((nbase + nt2 * 16) * 72 + koff) * 2);
                #pragma unroll
                for (int mf = 0; mf < 2; mf++) {
                    mma16816(o[mf][nt2 * 2],     pf[mf][ks][0], pf[mf][ks][1],
                             pf[mf][ks][2], pf[mf][ks][3], v4[0], v4[1]);
                    mma16816(o[mf][nt2 * 2 + 1], pf[mf][ks][0], pf[mf][ks][1],
                             pf[mf][ks][2], pf[mf][ks][3], v4[2], v4[3]);
                }
            }
            u32 v4[4];
            ldsm4(v4[0], v4[1], v4[2], v4[3], vB + ((nbase + 64) * 72 + koff) * 2);
            #pragma unroll
            for (int mf = 0; mf < 2; mf++)
                mma16816(o[mf][8], pf[mf][ks][0], pf[mf][ks][1],
                         pf[mf][ks][2], pf[mf][ks][3], v4[0], v4[1]);
        }
    }

    int b = bh >> 4, h = bh & 15;
    #pragma unroll
    for (int mf = 0; mf < 2; mf++) {
        float l0r = __shfl_sync(0xffffffffu, o[mf][8][0], lane & ~3);
        float l1r = __shfl_sync(0xffffffffu, o[mf][8][2], lane & ~3);
        float inv0 = 1.0f / l0r, inv1 = 1.0f / l1r;
        int r0 = q0 + wid * 32 + mf * 16 + (lane >> 2);
        int r1 = r0 + 8;
        #pragma unroll
        for (int nt = 0; nt < 8; nt++) {
            int e = h * HD + nt * 8 + (lane & 3) * 2;
            *(u32*)(g_C + ((size_t)b * SEQ + r0) * DM + e)
                = pack2(o[mf][nt][0] * inv0, o[mf][nt][1] * inv0);
            *(u32*)(g_C + ((size_t)b * SEQ + r1) * DM + e)
                = pack2(o[mf][nt][2] * inv1, o[mf][nt][3] * inv1);
        }
    }
}

// ---------------------------------------------------------------------------
// Output projection: grid (16 m-tiles, 8 n-tiles), 1-pass, 256x128
// ---------------------------------------------------------------------------
__global__ __launch_bounds__(256, 1)
void k_gemm_out(const float* __restrict__ bp, float* __restrict__ out)
{
    extern __shared__ char smch[];
    u32 smb = smem_u32(smch);
    int tid = threadIdx.x, lane = tid & 31, wid = tid >> 5;
    int wm = wid >> 1, wn = wid & 1;

    int m0 = blockIdx.x * 256;
    int n0 = blockIdx.y * 128;

    float acc[4][8][4] = {};
    proj_mainloop(smb, g_C + (size_t)m0 * DM, g_Wp + (size_t)n0 * DM,
                  acc, tid, lane, wm, wn);

    #pragma unroll
    for (int mt = 0; mt < 4; mt++)
        #pragma unroll
        for (int nt = 0; nt < 8; nt++) {
            int m = m0 + wm * 64 + mt * 16 + (lane >> 2);
            int n = n0 + wn * 64 + nt * 8 + (lane & 3) * 2;
            float b0 = bp[n], b1 = bp[n + 1];
            float2 v0 = { acc[mt][nt][0] + b0, acc[mt][nt][1] + b1 };
            float2 v1 = { acc[mt][nt][2] + b0, acc[mt][nt][3] + b1 };
            *(float2*)(out + (size_t)m * DM + n) = v0;
            *(float2*)(out + (size_t)(m + 8) * DM + n) = v1;
        }
}

// ---------------------------------------------------------------------------
extern "C" void kernel_launch(void* const* d_in, const int* in_sizes, int n_in,
                              void* d_out, int out_size)
{
    (void)in_sizes; (void)n_in; (void)out_size;
    const float* x  = (const float*)d_in[0];
    const float* Wq = (const float*)d_in[1];
    const float* Wk = (const float*)d_in[2];
    const float* Wv = (const float*)d_in[3];
    const float* bq = (const float*)d_in[4];
    const float* bk = (const float*)d_in[5];
    const float* bv = (const float*)d_in[6];
    const float* Wp = (const float*)d_in[7];
    const float* bp = (const float*)d_in[8];
    float* out = (float*)d_out;

    cudaFuncSetAttribute(k_gemm_qkv, cudaFuncAttributeMaxDynamicSharedMemorySize, P_SMEM_BYTES);
    cudaFuncSetAttribute(k_attn,     cudaFuncAttributeMaxDynamicSharedMemorySize, A_SMEM_BYTES);
    cudaFuncSetAttribute(k_gemm_out, cudaFuncAttributeMaxDynamicSharedMemorySize, P_SMEM_BYTES);

    k_prep<<<(MROWS * DM + DM * DM + 255) / 256, 256>>>(x, Wp);
    dim3 tgrid(DM / 32, HD / 32, 48);
    dim3 tblk(32, 8);
    k_split_w_t<<<tgrid, tblk>>>(Wq, Wk, Wv);

    k_gemm_qkv<<<dim3(MROWS / 256, 24), 256, P_SMEM_BYTES>>>(bq, bk, bv);
    k_attn<<<dim3(SEQ / 128, BH), 128, A_SMEM_BYTES>>>();
    k_gemm_out<<<dim3(MROWS / 256, DM / 128), 256, P_SMEM_BYTES>>>(bp, out);
}

// round 17
// speedup vs baseline: 1.1915x; 1.1915x over previous
#include <cuda_runtime.h>
#include <cuda_fp16.h>

typedef unsigned int u32;

#define BATCH 2
#define SEQ   2048
#define DM    1024
#define NH    16
#define HD    64
#define MROWS 4096
#define BH    32

#define QSCALE 0.18033688011112042f

// ---------------------------------------------------------------------------
__device__ __align__(128) __half g_x  [(size_t)MROWS * DM];
__device__ __align__(128) __half g_Wh [(size_t)48 * HD * DM];  // [(proj*16+h)*64+e][d]
__device__ __align__(128) __half g_Wp [(size_t)DM * DM];       // [n][k]
__device__ __align__(128) __half g_Q  [(size_t)BH * SEQ * HD]; // pre-scaled QSCALE
__device__ __align__(128) __half g_K  [(size_t)BH * SEQ * HD];
__device__ __align__(128) __half g_Vt [(size_t)BH * HD * SEQ]; // [bh][e][s]
__device__ __align__(128) __half g_C  [(size_t)MROWS * DM];

// ---------------------------------------------------------------------------
__device__ __forceinline__ u32 smem_u32(const void* p) {
    u32 a;
    asm("{ .reg .u64 t; cvta.to.shared.u64 t, %1; cvt.u32.u64 %0, t; }" : "=r"(a) : "l"(p));
    return a;
}
__device__ __forceinline__ void mma16816(float c[4], u32 a0, u32 a1, u32 a2, u32 a3,
                                         u32 b0, u32 b1) {
    asm volatile("mma.sync.aligned.m16n8k16.row.col.f32.f16.f16.f32 "
                 "{%0,%1,%2,%3},{%4,%5,%6,%7},{%8,%9},{%0,%1,%2,%3};"
                 : "+f"(c[0]), "+f"(c[1]), "+f"(c[2]), "+f"(c[3])
                 : "r"(a0), "r"(a1), "r"(a2), "r"(a3), "r"(b0), "r"(b1));
}
__device__ __forceinline__ void ldsm4(u32& r0, u32& r1, u32& r2, u32& r3, u32 addr) {
    asm volatile("ldmatrix.sync.aligned.m8n8.x4.shared.b16 {%0,%1,%2,%3},[%4];"
                 : "=r"(r0), "=r"(r1), "=r"(r2), "=r"(r3) : "r"(addr));
}
__device__ __forceinline__ void cpa16(u32 dst, const void* src) {
    asm volatile("cp.async.ca.shared.global [%0],[%1],16;" :: "r"(dst), "l"(src));
}
#define CP_COMMIT() asm volatile("cp.async.commit_group;" ::: "memory")
#define CP_WAIT0()  asm volatile("cp.async.wait_group 0;" ::: "memory")
#define CP_WAIT1()  asm volatile("cp.async.wait_group 1;" ::: "memory")

__device__ __forceinline__ u32 pack2(float a, float b) {
    __half2 h = __floats2half2_rn(a, b);
    return *reinterpret_cast<u32*>(&h);
}
__device__ __forceinline__ u32 exp2x2(float d0, float d1) {
    u32 h = pack2(d0, d1), r;
    asm("ex2.approx.f16x2 %0, %1;" : "=r"(r) : "r"(h));
    return r;
}

// ---------------------------------------------------------------------------
// Prep
// ---------------------------------------------------------------------------
__global__ void k_prep(const float* __restrict__ x, const float* __restrict__ Wp) {
    int i = blockIdx.x * 256 + threadIdx.x;
    if (i < MROWS * DM) g_x[i] = __float2half_rn(x[i]);
    int j = i - MROWS * DM;
    if (j >= 0 && j < DM * DM) g_Wp[j] = __float2half_rn(Wp[j]);
}
__global__ void k_split_w_t(const float* __restrict__ Wq, const float* __restrict__ Wk,
                            const float* __restrict__ Wv) {
    __shared__ float t[32][33];
    int d0 = blockIdx.x * 32, e0 = blockIdx.y * 32;
    int ph = blockIdx.z, proj = ph >> 4, h = ph & 15;
    const float* W = (proj == 0) ? Wq : (proj == 1) ? Wk : Wv;
    const float* src = W + ((size_t)h * DM + d0) * HD + e0;
    for (int j = threadIdx.y; j < 32; j += 8)
        t[j][threadIdx.x] = src[(size_t)j * HD + threadIdx.x];
    __syncthreads();
    size_t ob = ((size_t)ph * HD + e0) * DM + d0;
    for (int j = threadIdx.y; j < 32; j += 8)
        g_Wh[ob + (size_t)j * DM + threadIdx.x] = __float2half_rn(t[threadIdx.x][j]);
}

// ---------------------------------------------------------------------------
// GEMM 128(M) x 128(N) x 1024, BK=32, 4 warps (2M x 2N), warp tile 64x64.
// 3-stage cp.async ring, block=128, 2 CTAs/SM.
// smem halves per stage: A 128x40 (5120) + B 128x40 (5120) = 10240.
// ---------------------------------------------------------------------------
#define P_STAGE 10240
#define P_SMEM_BYTES (3 * P_STAGE * 2)

__device__ __forceinline__ void proj_issue(u32 smb, const __half* A, const __half* B,
                                           int k0, int stage, int tid)
{
    u32 a = smb + (stage * P_STAGE) * 2;
    u32 b = a + 5120 * 2;
    #pragma unroll
    for (int i = tid; i < 1024; i += 128) {
        int r = (i & 511) >> 2, c8 = (i & 3) * 8;
        if (i < 512) cpa16(a + (r * 40 + c8) * 2, A + (size_t)r * DM + k0 + c8);
        else         cpa16(b + (r * 40 + c8) * 2, B + (size_t)r * DM + k0 + c8);
    }
}

__device__ __forceinline__ void proj_compute(u32 smb, int stage, int lane, int wm, int wn,
                                             float acc[4][8][4])
{
    u32 aB = smb + (stage * P_STAGE) * 2;
    u32 bB = aB + 5120 * 2;
    #pragma unroll
    for (int kk = 0; kk < 32; kk += 16) {
        u32 a4[4][4];
        int arow_off = ((wm * 64 + (lane & 15)) * 40 + kk + ((lane >> 4) << 3)) * 2;
        #pragma unroll
        for (int mt = 0; mt < 4; mt++)
            ldsm4(a4[mt][0], a4[mt][1], a4[mt][2], a4[mt][3], aB + arow_off + mt * 16 * 40 * 2);
        int nbase = wn * 64 + ((lane >> 4) << 3) + (lane & 7);
        int koff = kk + (((lane >> 3) & 1) << 3);
        #pragma unroll
        for (int nt2 = 0; nt2 < 4; nt2++) {
            u32 b4[4];
            ldsm4(b4[0], b4[1], b4[2], b4[3], bB + ((nbase + nt2 * 16) * 40 + koff) * 2);
            #pragma unroll
            for (int hn = 0; hn < 2; hn++) {
                int nt = nt2 * 2 + hn;
                #pragma unroll
                for (int mt = 0; mt < 4; mt++)
                    mma16816(acc[mt][nt], a4[mt][0], a4[mt][1], a4[mt][2], a4[mt][3],
                             b4[hn * 2], b4[hn * 2 + 1]);
            }
        }
    }
}

__device__ __forceinline__ void proj_mainloop(u32 smb, const __half* A, const __half* B,
                                              float acc[4][8][4], int tid, int lane,
                                              int wm, int wn)
{
    proj_issue(smb, A, B, 0, 0, tid);
    CP_COMMIT();
    proj_issue(smb, A, B, 32, 1, tid);
    CP_COMMIT();
    for (int st = 0; st < 32; st++) {
        if (st < 31) CP_WAIT1(); else CP_WAIT0();
        __syncthreads();
        if (st + 2 < 32) {
            proj_issue(smb, A, B, (st + 2) * 32, (st + 2) % 3, tid);
            CP_COMMIT();
        }
        proj_compute(smb, st % 3, lane, wm, wn, acc);
    }
    __syncthreads();
}

// ---------------------------------------------------------------------------
// QKV GEMM: grid (32 m-tiles, 24), block 128. All 1-pass fp16.
// ---------------------------------------------------------------------------
__global__ __launch_bounds__(128, 2)
void k_gemm_qkv(const float* __restrict__ bq, const float* __restrict__ bk,
                const float* __restrict__ bv)
{
    extern __shared__ char smch[];
    u32 smb = smem_u32(smch);
    int tid = threadIdx.x, lane = tid & 31, wid = tid >> 5;
    int wm = wid >> 1, wn = wid & 1;

    int m0 = blockIdx.x * 128;
    int py = blockIdx.y, proj = py >> 3, n0 = (py & 7) * 128;

    const __half* B = g_Wh + ((size_t)proj * 16 * HD + n0) * DM;

    float acc[4][8][4] = {};
    proj_mainloop(smb, g_x + (size_t)m0 * DM, B, acc, tid, lane, wm, wn);

    const float* bias = ((proj == 0) ? bq : (proj == 1 ? bk : bv));

    if (proj < 2) {
        float scale = (proj == 0) ? QSCALE : 1.0f;
        __half* oq = (proj == 0 ? g_Q : g_K);
        #pragma unroll
        for (int mt = 0; mt < 4; mt++) {
            #pragma unroll
            for (int nt = 0; nt < 8; nt++) {
                int m = m0 + wm * 64 + mt * 16 + (lane >> 2);
                int eg = n0 + wn * 64 + nt * 8 + (lane & 3) * 2;
                int h = eg >> 6, e = eg & 63;
                float be0 = bias[eg], be1 = bias[eg + 1];
                float v0 = (acc[mt][nt][0] + be0) * scale;
                float v1 = (acc[mt][nt][1] + be1) * scale;
                float v2 = (acc[mt][nt][2] + be0) * scale;
                float v3 = (acc[mt][nt][3] + be1) * scale;
                int b0 = m >> 11, s0 = m & 2047;
                int m2 = m + 8, b2 = m2 >> 11, s2 = m2 & 2047;
                *(u32*)(oq + ((size_t)(b0 * NH + h) * SEQ + s0) * HD + e) = pack2(v0, v1);
                *(u32*)(oq + ((size_t)(b2 * NH + h) * SEQ + s2) * HD + e) = pack2(v2, v3);
            }
        }
    } else {
        // V: stage transposed [128 e][128 m] tile in smem, coalesced stores
        __half* sv = (__half*)smch;
        #pragma unroll
        for (int mt = 0; mt < 4; mt++) {
            #pragma unroll
            for (int nt = 0; nt < 8; nt++) {
                int ml = wm * 64 + mt * 16 + (lane >> 2);
                int el = wn * 64 + nt * 8 + (lane & 3) * 2;
                float be0 = bias[n0 + el], be1 = bias[n0 + el + 1];
                sv[el * 128 + ml]            = __float2half_rn(acc[mt][nt][0] + be0);
                sv[(el + 1) * 128 + ml]      = __float2half_rn(acc[mt][nt][1] + be1);
                sv[el * 128 + ml + 8]        = __float2half_rn(acc[mt][nt][2] + be0);
                sv[(el + 1) * 128 + ml + 8]  = __float2half_rn(acc[mt][nt][3] + be1);
            }
        }
        __syncthreads();
        int b = m0 >> 11, s0 = m0 & 2047;
        for (int i = tid; i < 128 * 64; i += 128) {
            int el = i >> 6, mp = i & 63;
            int eg = n0 + el, h = eg >> 6, e = eg & 63;
            ((u32*)(g_Vt + ((size_t)(b * NH + h) * HD + e) * SEQ + s0))[mp]
                = ((u32*)(sv + el * 128))[mp];
        }
    }
}

// ---------------------------------------------------------------------------
// Flash attention: unchanged (96 us, tensor 62%).
// ---------------------------------------------------------------------------
#define A_STAGE 10368
#define A_SMEM_BYTES ((9216 + 3 * A_STAGE) * 2)

__device__ __forceinline__ void attn_issue(u32 smb,
    const __half* K, const __half* V, int c0, int stage, int tid)
{
    u32 kb = smb + (9216 + stage * A_STAGE) * 2;
    u32 vb = kb + 4608 * 2;
    #pragma unroll
    for (int i = tid; i < 512; i += 128) {
        int r = i >> 3, c8 = (i & 7) * 8;
        cpa16(kb + (r * 72 + c8) * 2, K + (size_t)(c0 + r) * HD + c8);
        cpa16(vb + (r * 72 + c8) * 2, V + (size_t)r * SEQ + c0 + c8);
    }
}

__global__ __launch_bounds__(128, 2)
void k_attn()
{
    extern __shared__ char smch[];
    u32 smb = smem_u32(smch);
    int tid = threadIdx.x, lane = tid & 31, wid = tid >> 5;

    int q0 = blockIdx.x * 128;
    int bh = blockIdx.y;
    const __half* Qp = g_Q + (size_t)bh * SEQ * HD;
    const __half* Kp = g_K + (size_t)bh * SEQ * HD;
    const __half* Vp = g_Vt + (size_t)bh * HD * SEQ;

    attn_issue(smb, Kp, Vp, 0, 0, tid);
    CP_COMMIT();
    attn_issue(smb, Kp, Vp, 64, 1, tid);
    CP_COMMIT();

    #pragma unroll
    for (int i = tid; i < 1024; i += 128) {
        int r = i >> 3, c8 = (i & 7) * 8;
        *(uint4*)(smch + (r * 72 + c8) * 2) = *(const uint4*)(Qp + (size_t)(q0 + r) * HD + c8);
    }
    for (int i = tid; i < 3 * 16 * 72; i += 128) {
        int stage = i / (16 * 72), rem = i % (16 * 72);
        int row = 64 + rem / 72, col = rem % 72;
        __half v = (row == 64) ? __float2half_rn(1.0f) : __float2half_rn(0.0f);
        *(__half*)(smch + (9216 + stage * A_STAGE + 4608 + row * 72 + col) * 2) = v;
    }
    __syncthreads();

    u32 qf[2][4][4];
    #pragma unroll
    for (int mf = 0; mf < 2; mf++)
        #pragma unroll
        for (int ks = 0; ks < 4; ks++) {
            u32 qoff = smb + ((wid * 32 + mf * 16 + (lane & 15)) * 72
                              + ks * 16 + ((lane >> 4) << 3)) * 2;
            ldsm4(qf[mf][ks][0], qf[mf][ks][1], qf[mf][ks][2], qf[mf][ks][3], qoff);
        }

    float o[2][9][4] = {};

    for (int it = 0; it < 32; it++) {
        int buf = it % 3;
        if (it < 31) CP_WAIT1(); else CP_WAIT0();
        __syncthreads();
        if (it + 2 < 32) {
            attn_issue(smb, Kp, Vp, (it + 2) * 64, (it + 2) % 3, tid);
            CP_COMMIT();
        }

        float s[2][8][4] = {};
        u32 kB = smb + (9216 + buf * A_STAGE) * 2;
        int nbase = ((lane >> 4) << 3) + (lane & 7);
        #pragma unroll
        for (int ks = 0; ks < 4; ks++) {
            int koff = ks * 16 + (((lane >> 3) & 1) << 3);
            #pragma unroll
            for (int nt2 = 0; nt2 < 4; nt2++) {
                u32 k4[4];
                ldsm4(k4[0], k4[1], k4[2], k4[3], kB + ((nbase + nt2 * 16) * 72 + koff) * 2);
                #pragma unroll
                for (int mf = 0; mf < 2; mf++) {
                    mma16816(s[mf][nt2 * 2],     qf[mf][ks][0], qf[mf][ks][1],
                             qf[mf][ks][2], qf[mf][ks][3], k4[0], k4[1]);
                    mma16816(s[mf][nt2 * 2 + 1], qf[mf][ks][0], qf[mf][ks][1],
                             qf[mf][ks][2], qf[mf][ks][3], k4[2], k4[3]);
                }
            }
        }

        u32 pf[2][4][4];
        #pragma unroll
        for (int mf = 0; mf < 2; mf++)
            #pragma unroll
            for (int ks = 0; ks < 4; ks++) {
                int t0 = 2 * ks, t1 = 2 * ks + 1;
                pf[mf][ks][0] = exp2x2(s[mf][t0][0], s[mf][t0][1]);
                pf[mf][ks][1] = exp2x2(s[mf][t0][2], s[mf][t0][3]);
                pf[mf][ks][2] = exp2x2(s[mf][t1][0], s[mf][t1][1]);
                pf[mf][ks][3] = exp2x2(s[mf][t1][2], s[mf][t1][3]);
            }

        u32 vB = kB + 4608 * 2;
        #pragma unroll
        for (int ks = 0; ks < 4; ks++) {
            int koff = ks * 16 + (((lane >> 3) & 1) << 3);
            #pragma unroll
            for (int nt2 = 0; nt2 < 4; nt2++) {
                u32 v4[4];
                ldsm4(v4[0], v4[1], v4[2], v4[3], vB + ((nbase + nt2 * 16) * 72 + koff) * 2);
                #pragma unroll
                for (int mf = 0; mf < 2; mf++) {
                    mma16816(o[mf][nt2 * 2],     pf[mf][ks][0], pf[mf][ks][1],
                             pf[mf][ks][2], pf[mf][ks][3], v4[0], v4[1]);
                    mma16816(o[mf][nt2 * 2 + 1], pf[mf][ks][0], pf[mf][ks][1],
                             pf[mf][ks][2], pf[mf][ks][3], v4[2], v4[3]);
                }
            }
            u32 v4[4];
            ldsm4(v4[0], v4[1], v4[2], v4[3], vB + ((nbase + 64) * 72 + koff) * 2);
            #pragma unroll
            for (int mf = 0; mf < 2; mf++)
                mma16816(o[mf][8], pf[mf][ks][0], pf[mf][ks][1],
                         pf[mf][ks][2], pf[mf][ks][3], v4[0], v4[1]);
        }
    }

    int b = bh >> 4, h = bh & 15;
    #pragma unroll
    for (int mf = 0; mf < 2; mf++) {
        float l0r = __shfl_sync(0xffffffffu, o[mf][8][0], lane & ~3);
        float l1r = __shfl_sync(0xffffffffu, o[mf][8][2], lane & ~3);
        float inv0 = 1.0f / l0r, inv1 = 1.0f / l1r;
        int r0 = q0 + wid * 32 + mf * 16 + (lane >> 2);
        int r1 = r0 + 8;
        #pragma unroll
        for (int nt = 0; nt < 8; nt++) {
            int e = h * HD + nt * 8 + (lane & 3) * 2;
            *(u32*)(g_C + ((size_t)b * SEQ + r0) * DM + e)
                = pack2(o[mf][nt][0] * inv0, o[mf][nt][1] * inv0);
            *(u32*)(g_C + ((size_t)b * SEQ + r1) * DM + e)
                = pack2(o[mf][nt][2] * inv1, o[mf][nt][3] * inv1);
        }
    }
}

// ---------------------------------------------------------------------------
// Output projection: grid (32 m-tiles, 8 n-tiles), block 128, 1-pass, 128x128
// ---------------------------------------------------------------------------
__global__ __launch_bounds__(128, 2)
void k_gemm_out(const float* __restrict__ bp, float* __restrict__ out)
{
    extern __shared__ char smch[];
    u32 smb = smem_u32(smch);
    int tid = threadIdx.x, lane = tid & 31, wid = tid >> 5;
    int wm = wid >> 1, wn = wid & 1;

    int m0 = blockIdx.x * 128;
    int n0 = blockIdx.y * 128;

    float acc[4][8][4] = {};
    proj_mainloop(smb, g_C + (size_t)m0 * DM, g_Wp + (size_t)n0 * DM,
                  acc, tid, lane, wm, wn);

    #pragma unroll
    for (int mt = 0; mt < 4; mt++)
        #pragma unroll
        for (int nt = 0; nt < 8; nt++) {
            int m = m0 + wm * 64 + mt * 16 + (lane >> 2);
            int n = n0 + wn * 64 + nt * 8 + (lane & 3) * 2;
            float b0 = bp[n], b1 = bp[n + 1];
            float2 v0 = { acc[mt][nt][0] + b0, acc[mt][nt][1] + b1 };
            float2 v1 = { acc[mt][nt][2] + b0, acc[mt][nt][3] + b1 };
            *(float2*)(out + (size_t)m * DM + n) = v0;
            *(float2*)(out + (size_t)(m + 8) * DM + n) = v1;
        }
}

// ---------------------------------------------------------------------------
extern "C" void kernel_launch(void* const* d_in, const int* in_sizes, int n_in,
                              void* d_out, int out_size)
{
    (void)in_sizes; (void)n_in; (void)out_size;
    const float* x  = (const float*)d_in[0];
    const float* Wq = (const float*)d_in[1];
    const float* Wk = (const float*)d_in[2];
    const float* Wv = (const float*)d_in[3];
    const float* bq = (const float*)d_in[4];
    const float* bk = (const float*)d_in[5];
    const float* bv = (const float*)d_in[6];
    const float* Wp = (const float*)d_in[7];
    const float* bp = (const float*)d_in[8];
    float* out = (float*)d_out;

    cudaFuncSetAttribute(k_gemm_qkv, cudaFuncAttributeMaxDynamicSharedMemorySize, P_SMEM_BYTES);
    cudaFuncSetAttribute(k_attn,     cudaFuncAttributeMaxDynamicSharedMemorySize, A_SMEM_BYTES);
    cudaFuncSetAttribute(k_gemm_out, cudaFuncAttributeMaxDynamicSharedMemorySize, P_SMEM_BYTES);

    k_prep<<<(MROWS * DM + DM * DM + 255) / 256, 256>>>(x, Wp);
    dim3 tgrid(DM / 32, HD / 32, 48);
    dim3 tblk(32, 8);
    k_split_w_t<<<tgrid, tblk>>>(Wq, Wk, Wv);

    k_gemm_qkv<<<dim3(MROWS / 128, 24), 128, P_SMEM_BYTES>>>(bq, bk, bv);
    k_attn<<<dim3(SEQ / 128, BH), 128, A_SMEM_BYTES>>>();
    k_gemm_out<<<dim3(MROWS / 128, DM / 128), 128, P_SMEM_BYTES>>>(bp, out);
}